// round 2
// baseline (speedup 1.0000x reference)
#include <cuda_runtime.h>
#include <cstdint>

#define NN   100000
#define NE   1600000
#define HIDV 64
#define ALPHA_C 0.1f
#define COEF_C  0.3f   // (1-ALPHA)/K = 0.9/3

// ---------------- scratch (device globals: no allocation allowed) ----------------
__device__ int   g_is64;             // 1 if edge_index is int64, 0 if int32
__device__ int   g_cnt[NN];          // in-degree (original edges, no self loop)
__device__ int   g_rowptr[NN + 1];   // CSR row pointers by dst
__device__ int   g_cursor[NN];       // scatter cursors
__device__ float g_dinv[NN];         // 1/sqrt(deg+1)
__device__ int   g_part[128];        // scan partials (98 blocks)
__device__ int   g_src[NE];          // CSR: source node per edge (sorted by dst)
__device__ float g_w[NE];            // CSR: dinv[src]*dinv[dst]
__device__ float g_h1[NN * HIDV];
__device__ float g_h2[NN * HIDV];
__device__ float g_acc[NN * HIDV];

// ---------------- dtype detection ----------------
// If edge_index is int64 (values < 100000), every odd 32-bit word is 0.
// If int32, odd words are uniform in [0, 100000): P(zero) = 1e-5.
__global__ void k_detect(const int* __restrict__ ei32) {
    if (threadIdx.x == 0 && blockIdx.x == 0) {
        int zeros = 0;
        #pragma unroll 1
        for (int k = 1; k < 129; k += 2) zeros += (ei32[k] == 0);
        g_is64 = (zeros >= 60) ? 1 : 0;
    }
}

__device__ __forceinline__ int edge_at(const void* ei, long long idx, int is64) {
    if (is64) return (int)((const long long*)ei)[idx];
    return ((const int*)ei)[idx];
}

// ---------------- CSR build ----------------
__global__ void k_zero() {
    int i = blockIdx.x * blockDim.x + threadIdx.x;
    if (i < NN) g_cnt[i] = 0;
}

__global__ void k_hist(const void* __restrict__ ei) {
    int e = blockIdx.x * blockDim.x + threadIdx.x;
    int is64 = g_is64;
    if (e < NE) {
        int dst = edge_at(ei, (long long)NE + e, is64);
        atomicAdd(&g_cnt[dst], 1);
    }
}

// block-local exclusive scan (1024 elems per block), partial sums to g_part
__global__ void k_scan_local() {
    __shared__ int s[1024];
    int tid = threadIdx.x;
    int i = blockIdx.x * 1024 + tid;
    int v = (i < NN) ? g_cnt[i] : 0;
    s[tid] = v;
    __syncthreads();
    #pragma unroll
    for (int off = 1; off < 1024; off <<= 1) {
        int t = (tid >= off) ? s[tid - off] : 0;
        __syncthreads();
        s[tid] += t;
        __syncthreads();
    }
    if (i < NN) g_rowptr[i] = s[tid] - v;   // local exclusive
    if (tid == 1023) g_part[blockIdx.x] = s[1023];
}

__global__ void k_scan_part(int nb) {
    if (threadIdx.x == 0 && blockIdx.x == 0) {
        int run = 0;
        for (int b = 0; b < nb; b++) { int t = g_part[b]; g_part[b] = run; run += t; }
        g_rowptr[NN] = run;   // == NE
    }
}

__global__ void k_finalize() {
    int i = blockIdx.x * blockDim.x + threadIdx.x;
    if (i < NN) {
        int rp = g_rowptr[i] + g_part[i >> 10];
        g_rowptr[i] = rp;
        g_cursor[i] = rp;
        g_dinv[i] = rsqrtf((float)(g_cnt[i] + 1));   // +1 self loop
    }
}

__global__ void k_scatter(const void* __restrict__ ei) {
    int e = blockIdx.x * blockDim.x + threadIdx.x;
    int is64 = g_is64;
    if (e < NE) {
        int src = edge_at(ei, e, is64);
        int dst = edge_at(ei, (long long)NE + e, is64);
        int pos = atomicAdd(&g_cursor[dst], 1);
        g_src[pos] = src;
        g_w[pos] = g_dinv[src] * g_dinv[dst];
    }
}

// ---------------- propagation: warp per dst row, float2 per lane ----------------
// IN: 0 = g_h1, 1 = g_h2, 2 = x        OUT: 0 = g_h1, 1 = g_h2
template <int IN, int OUT, bool INIT>
__global__ void k_spmm(const float* __restrict__ x) {
    int row  = blockIdx.x * (blockDim.x >> 5) + (threadIdx.x >> 5);
    if (row >= NN) return;
    int lane = threadIdx.x & 31;

    const float2* hin  = (IN == 0) ? (const float2*)g_h1
                       : (IN == 1) ? (const float2*)g_h2
                       :             (const float2*)x;
    float2* hout = (OUT == 0) ? (float2*)g_h1 : (float2*)g_h2;

    int beg = g_rowptr[row];
    int end = g_rowptr[row + 1];
    float dv = g_dinv[row];

    int o = row * 32 + lane;
    float2 self = __ldg(&hin[o]);
    float2 sum;
    sum.x = dv * dv * self.x;   // self-loop term: dinv[i]^2 * h[i]
    sum.y = dv * dv * self.y;

    for (int e = beg; e < end; e++) {
        int   s = __ldg(&g_src[e]);
        float w = __ldg(&g_w[e]);
        float2 v = __ldg(&hin[s * 32 + lane]);
        sum.x += w * v.x;
        sum.y += w * v.y;
    }
    hout[o] = sum;

    float2 a;
    if (INIT) { a.x = ALPHA_C * self.x; a.y = ALPHA_C * self.y; }  // hin == x here
    else      { a = ((float2*)g_acc)[o]; }
    a.x += COEF_C * sum.x;
    a.y += COEF_C * sum.y;
    ((float2*)g_acc)[o] = a;
}

// mean conv over original edges, relu(acc) applied on the fly, fused residual+relu
__global__ void k_mean(const float* __restrict__ x, float* __restrict__ out) {
    int row  = blockIdx.x * (blockDim.x >> 5) + (threadIdx.x >> 5);
    if (row >= NN) return;
    int lane = threadIdx.x & 31;

    int beg = g_rowptr[row];
    int end = g_rowptr[row + 1];
    const float2* a2 = (const float2*)g_acc;

    float2 sum = {0.f, 0.f};
    for (int e = beg; e < end; e++) {
        int s = __ldg(&g_src[e]);
        float2 v = __ldg(&a2[s * 32 + lane]);
        sum.x += fmaxf(v.x, 0.f);
        sum.y += fmaxf(v.y, 0.f);
    }
    float inv = 1.0f / fmaxf((float)(end - beg), 1.0f);

    int o = row * 32 + lane;
    float2 xx = __ldg(&((const float2*)x)[o]);
    float2 r;
    r.x = fmaxf(sum.x * inv + xx.x, 0.f);
    r.y = fmaxf(sum.y * inv + xx.y, 0.f);
    ((float2*)out)[o] = r;
}

// ---------------- launch ----------------
extern "C" void kernel_launch(void* const* d_in, const int* in_sizes, int n_in,
                              void* d_out, int out_size) {
    const float* x  = (const float*)d_in[0];
    const void*  ei = (const void*)d_in[1];
    float* out = (float*)d_out;

    k_detect<<<1, 32>>>((const int*)ei);
    k_zero<<<(NN + 255) / 256, 256>>>();
    k_hist<<<(NE + 255) / 256, 256>>>(ei);
    int nb = (NN + 1023) / 1024;   // 98
    k_scan_local<<<nb, 1024>>>();
    k_scan_part<<<1, 32>>>(nb);
    k_finalize<<<(NN + 255) / 256, 256>>>();
    k_scatter<<<(NE + 255) / 256, 256>>>(ei);

    const int WPB = 8;                       // warps (rows) per block
    int grid = (NN + WPB - 1) / WPB;         // 12500
    // SSG hops: out = 0.1*x + 0.3*(A x + A^2 x + A^3 x)
    k_spmm<2, 0, true ><<<grid, WPB * 32>>>(x);   // x   -> h1, acc = 0.1x + 0.3h1
    k_spmm<0, 1, false><<<grid, WPB * 32>>>(x);   // h1  -> h2, acc += 0.3h2
    k_spmm<1, 0, false><<<grid, WPB * 32>>>(x);   // h2  -> h1, acc += 0.3h1'
    // mean conv on relu(acc) + residual + relu
    k_mean<<<grid, WPB * 32>>>(x, out);
}